// round 2
// baseline (speedup 1.0000x reference)
#include <cuda_runtime.h>
#include <cstdint>

#define MAX_N 100000
#define IN_DIM 192
#define NEG_SLOPE 0.2f

// Scratch (allocation-free rule: __device__ globals).
// g_rec[n] = {xproj0, xproj1, a_src, a_dst}
// g_acc[n] = {sum e*xp0, sum e*xp1, sum e, pad}
__device__ float4 g_rec[MAX_N];
__device__ float4 g_acc[MAX_N];
__device__ int    g_is64;   // 1 if edge_index is int64, 0 if int32

// ---------------------------------------------------------------------------
// Detector: decide whether the edge_index buffer holds int64 or int32.
// For int64 indices < 2^31, every odd 32-bit word is 0. For an int32 index
// array, odd words are random indices — 2048 consecutive zeros is impossible
// for this data. Deterministic: same input -> same flag.
// ---------------------------------------------------------------------------
__global__ void detect_init_kernel(int assume64) { g_is64 = assume64; }

__global__ void detect_kernel(const int* __restrict__ eidx_w, int nwords)
{
    int i = blockIdx.x * blockDim.x + threadIdx.x;     // sample index
    int w = 2 * i + 1;                                  // odd word position
    if (w < nwords) {
        if (eidx_w[w] != 0) g_is64 = 0;                 // racy all-write-0: fine
    }
}

// ---------------------------------------------------------------------------
// Kernel 1: projection + per-node logits + self-loop init of accumulator.
// One warp per node; 8 warps (256 threads) per block.
// ---------------------------------------------------------------------------
__global__ __launch_bounds__(256)
void gat_project_kernel(const float* __restrict__ x,
                        const float* __restrict__ W,       // [IN_DIM,2]
                        const float* __restrict__ att_src, // [2]
                        const float* __restrict__ att_dst, // [2]
                        int N)
{
    int warp_id = (blockIdx.x * blockDim.x + threadIdx.x) >> 5;
    int lane = threadIdx.x & 31;
    if (warp_id >= N) return;

    const float* xrow = x + (size_t)warp_id * IN_DIM;
    float p0 = 0.f, p1 = 0.f;
#pragma unroll
    for (int j = 0; j < IN_DIM / 32; j++) {
        int k = lane + 32 * j;
        float xv = __ldg(xrow + k);
        p0 += xv * __ldg(W + 2 * k + 0);
        p1 += xv * __ldg(W + 2 * k + 1);
    }
#pragma unroll
    for (int off = 16; off > 0; off >>= 1) {
        p0 += __shfl_down_sync(0xffffffffu, p0, off);
        p1 += __shfl_down_sync(0xffffffffu, p1, off);
    }

    if (lane == 0) {
        float as0 = __ldg(att_src + 0), as1 = __ldg(att_src + 1);
        float ad0 = __ldg(att_dst + 0), ad1 = __ldg(att_dst + 1);
        float a_s = p0 * as0 + p1 * as1;
        float a_d = p0 * ad0 + p1 * ad1;
        g_rec[warp_id] = make_float4(p0, p1, a_s, a_d);
        // self-loop edge (src == dst == n)
        float alpha = a_s + a_d;
        alpha = (alpha >= 0.f) ? alpha : NEG_SLOPE * alpha;
        float ev = __expf(alpha);
        g_acc[warp_id] = make_float4(ev * p0, ev * p1, ev, 0.f);
    }
}

// ---------------------------------------------------------------------------
// Kernel 2: single pass over edges.
// alpha = leakyrelu(a_src[s] + a_dst[d]); e = exp(alpha)
// acc[d] += {e*xp0[s], e*xp1[s], e, 0}  via one red.global.add.v4.f32
// (max-subtraction elided: softmax is scale-invariant; exp(alpha) cannot
//  overflow fp32 for this data distribution)
// ---------------------------------------------------------------------------
__global__ __launch_bounds__(256)
void gat_edge_kernel(const void* __restrict__ edge_index, int E, int N)
{
    const float* __restrict__ recf = (const float*)g_rec;

    int e = blockIdx.x * blockDim.x + threadIdx.x;
    if (e >= E) return;

    int s, d;
    if (g_is64) {
        const long long* ei = (const long long*)edge_index;
        s = (int)ei[e];
        d = (int)ei[E + e];
    } else {
        const int* ei = (const int*)edge_index;
        s = ei[e];
        d = ei[E + e];
    }
    if ((unsigned)s >= (unsigned)N || (unsigned)d >= (unsigned)N) return;

    float4 rs = g_rec[s];                 // {xp0, xp1, a_src, a_dst}
    float ad  = __ldg(recf + 4 * d + 3);  // a_dst of target, 4B gather (L2-hit)

    float alpha = rs.z + ad;
    alpha = (alpha >= 0.f) ? alpha : NEG_SLOPE * alpha;
    float ev = __expf(alpha);

    float v0 = ev * rs.x;
    float v1 = ev * rs.y;
    asm volatile("red.global.add.v4.f32 [%0], {%1, %2, %3, %4};"
                 :: "l"(&g_acc[d]), "f"(v0), "f"(v1), "f"(ev), "f"(0.f)
                 : "memory");
}

// ---------------------------------------------------------------------------
// Kernel 3: normalize + bias -> output [N,2] float32
// ---------------------------------------------------------------------------
__global__ __launch_bounds__(256)
void gat_final_kernel(float* __restrict__ out,
                      const float* __restrict__ bias,
                      int N)
{
    int n = blockIdx.x * blockDim.x + threadIdx.x;
    if (n >= N) return;
    float4 a = g_acc[n];
    float inv = 1.0f / (a.z + 1e-16f);
    float b0 = __ldg(bias + 0), b1 = __ldg(bias + 1);
    float2 o = make_float2(a.x * inv + b0, a.y * inv + b1);
    ((float2*)out)[n] = o;
}

// ---------------------------------------------------------------------------
// Input identification by element count (robust to metadata ordering):
//   x          = largest (N*192)
//   edge_index = 2nd largest (2E int64-as-elems, or 2E int32, or 4E int32 words)
//   edge_attr  = 3rd largest (E)
//   W          = size 384
//   att_src, att_dst, bias = the three size-2 tensors, in order of appearance
// ---------------------------------------------------------------------------
extern "C" void kernel_launch(void* const* d_in, const int* in_sizes, int n_in,
                              void* d_out, int out_size)
{
    // ---- identify inputs by size ----
    int i_x = -1, i_eidx = -1, i_attr = -1, i_W = -1;
    int small[3] = {-1, -1, -1};
    int nsmall = 0;
    // three largest
    {
        long long best = -1; // x
        for (int i = 0; i < n_in; i++)
            if (in_sizes[i] > best) { best = in_sizes[i]; i_x = i; }
        best = -1;
        for (int i = 0; i < n_in; i++)
            if (i != i_x && in_sizes[i] > best) { best = in_sizes[i]; i_eidx = i; }
        best = -1;
        for (int i = 0; i < n_in; i++)
            if (i != i_x && i != i_eidx && in_sizes[i] > best) { best = in_sizes[i]; i_attr = i; }
    }
    for (int i = 0; i < n_in; i++) {
        if (i == i_x || i == i_eidx || i == i_attr) continue;
        if (in_sizes[i] > 16) { i_W = i; }
        else if (nsmall < 3) { small[nsmall++] = i; }
    }

    const float* x        = (const float*)d_in[i_x];
    const void*  eidx     = d_in[i_eidx];
    const float* W        = (const float*)d_in[i_W];
    const float* att_src  = (const float*)d_in[small[0]];
    const float* att_dst  = (const float*)d_in[small[1]];
    const float* bias     = (const float*)d_in[small[2]];
    float* out            = (float*)d_out;

    int N = in_sizes[i_x] / IN_DIM;
    int E = in_sizes[i_attr];                 // edge_attr is [E,1]
    int eidx_elems = in_sizes[i_eidx];

    // ---- edge_index dtype resolution ----
    if (eidx_elems == 4 * E) {
        // int64 data reported as int32 word count
        detect_init_kernel<<<1, 1>>>(1);
    } else {
        // ratio 2: int32 pairs OR int64 reported as int64 element count.
        // Detect on device: int64 => odd 32-bit words of src region all zero.
        detect_init_kernel<<<1, 1>>>(1);
        int nsample = 2048;
        if (2 * nsample > 2 * E) nsample = E;   // clamp (tiny-E safety)
        detect_kernel<<<(nsample + 255) / 256, 256>>>((const int*)eidx, 2 * E);
    }

    // K1: one warp per node, 8 warps per block
    int blocks1 = (N + 7) / 8;
    gat_project_kernel<<<blocks1, 256>>>(x, W, att_src, att_dst, N);

    // K2: one edge per thread
    int blocks2 = (E + 255) / 256;
    gat_edge_kernel<<<blocks2, 256>>>(eidx, E, N);

    // K3: normalize + bias
    int blocks3 = (N + 255) / 256;
    gat_final_kernel<<<blocks3, 256>>>(out, bias, N);
}

// round 3
// speedup vs baseline: 1.1661x; 1.1661x over previous
#include <cuda_runtime.h>
#include <cstdint>

#define MAX_N 100000
#define IN_DIM 192
#define NEG_SLOPE 0.2f
#define EDGE_ILP 4

// Scratch (allocation-free rule: __device__ globals).
// g_rec[n] = {xproj0, xproj1, a_src, a_dst}
// g_acc[n] = {sum e*xp0, sum e*xp1, sum e, pad}
__device__ float4 g_rec[MAX_N];
__device__ float4 g_acc[MAX_N];
__device__ int    g_is64;   // 1 if edge_index is int64, 0 if int32

// ---------------------------------------------------------------------------
// Detector (single launch, single block): decide int64 vs int32 edge_index.
// int64 indices < 2^31 have all-zero odd 32-bit words; random int32 indices
// cannot be all zero across 2048 samples. assume64 with nwords=0 => just set.
// ---------------------------------------------------------------------------
__global__ void detect_kernel(const int* __restrict__ w, int nwords, int assume64)
{
    __shared__ int flag;
    if (threadIdx.x == 0) flag = assume64;
    __syncthreads();
    if (nwords > 0) {
        for (int i = threadIdx.x; i < 2048; i += blockDim.x) {
            int p = 2 * i + 1;
            if (p < nwords && w[p] != 0) flag = 0;   // all racers write 0: fine
        }
    }
    __syncthreads();
    if (threadIdx.x == 0) g_is64 = flag;
}

// ---------------------------------------------------------------------------
// Kernel 1: projection + logits + self-loop init.
// Persistent warp loop: W hoisted into 3 float4 registers per lane (loaded
// once), each node costs 3x LDG.64 + reduction. DRAM-bound by design.
// ---------------------------------------------------------------------------
__global__ __launch_bounds__(256)
void gat_project_kernel(const float* __restrict__ x,
                        const float* __restrict__ W,       // [IN_DIM,2]
                        const float* __restrict__ att_src, // [2]
                        const float* __restrict__ att_dst, // [2]
                        int N)
{
    int lane  = threadIdx.x & 31;
    int warp  = (blockIdx.x * blockDim.x + threadIdx.x) >> 5;
    int nwarp = (gridDim.x * blockDim.x) >> 5;

    // W as float4: index q covers rows 2q,2q+1 -> {W[2q][0],W[2q][1],W[2q+1][0],W[2q+1][1]}
    const float4* W4 = (const float4*)W;
    float4 w0 = __ldg(W4 + lane);
    float4 w1 = __ldg(W4 + lane + 32);
    float4 w2 = __ldg(W4 + lane + 64);
    float as0 = __ldg(att_src + 0), as1 = __ldg(att_src + 1);
    float ad0 = __ldg(att_dst + 0), ad1 = __ldg(att_dst + 1);

    for (int n = warp; n < N; n += nwarp) {
        const float2* xr = (const float2*)(x + (size_t)n * IN_DIM);
        float2 x0 = __ldg(xr + lane);
        float2 x1 = __ldg(xr + lane + 32);
        float2 x2 = __ldg(xr + lane + 64);

        float p0 = x0.x * w0.x + x0.y * w0.z
                 + x1.x * w1.x + x1.y * w1.z
                 + x2.x * w2.x + x2.y * w2.z;
        float p1 = x0.x * w0.y + x0.y * w0.w
                 + x1.x * w1.y + x1.y * w1.w
                 + x2.x * w2.y + x2.y * w2.w;

#pragma unroll
        for (int off = 16; off > 0; off >>= 1) {
            p0 += __shfl_xor_sync(0xffffffffu, p0, off);
            p1 += __shfl_xor_sync(0xffffffffu, p1, off);
        }

        if (lane == 0) {
            float a_s = p0 * as0 + p1 * as1;
            float a_d = p0 * ad0 + p1 * ad1;
            g_rec[n] = make_float4(p0, p1, a_s, a_d);
            float alpha = a_s + a_d;                  // self-loop edge
            alpha = (alpha >= 0.f) ? alpha : NEG_SLOPE * alpha;
            float ev = __expf(alpha);
            g_acc[n] = make_float4(ev * p0, ev * p1, ev, 0.f);
        }
    }
}

// ---------------------------------------------------------------------------
// Kernel 2: single fused pass over edges, ILP=4.
// Front-batch 8 index loads -> 8 independent gathers -> 4 v4 reductions.
// (softmax max-subtraction elided: scale-invariant; fp32-safe here)
// ---------------------------------------------------------------------------
__global__ __launch_bounds__(256)
void gat_edge_kernel(const void* __restrict__ edge_index, int E, int N)
{
    const float* __restrict__ recf = (const float*)g_rec;
    int base  = blockIdx.x * (256 * EDGE_ILP) + threadIdx.x;
    int is64  = g_is64;

    int s[EDGE_ILP], d[EDGE_ILP];
#pragma unroll
    for (int i = 0; i < EDGE_ILP; i++) {
        int e = base + i * 256;
        s[i] = -1; d[i] = -1;
        if (e < E) {
            if (is64) {
                const long long* ei = (const long long*)edge_index;
                s[i] = (int)ei[e];
                d[i] = (int)ei[E + e];
            } else {
                const int* ei = (const int*)edge_index;
                s[i] = ei[e];
                d[i] = ei[E + e];
            }
        }
    }

    float4 rs[EDGE_ILP];
    float  ad[EDGE_ILP];
#pragma unroll
    for (int i = 0; i < EDGE_ILP; i++) {
        bool ok = (unsigned)s[i] < (unsigned)N && (unsigned)d[i] < (unsigned)N;
        if (ok) {
            rs[i] = g_rec[s[i]];                  // 16B gather (L1/L2)
            ad[i] = __ldg(recf + 4 * d[i] + 3);   // 4B gather (same array -> reuse)
        }
    }

#pragma unroll
    for (int i = 0; i < EDGE_ILP; i++) {
        bool ok = (unsigned)s[i] < (unsigned)N && (unsigned)d[i] < (unsigned)N;
        if (ok) {
            float alpha = rs[i].z + ad[i];
            alpha = (alpha >= 0.f) ? alpha : NEG_SLOPE * alpha;
            float ev = __expf(alpha);
            float v0 = ev * rs[i].x;
            float v1 = ev * rs[i].y;
            asm volatile("red.global.add.v4.f32 [%0], {%1, %2, %3, %4};"
                         :: "l"(&g_acc[d[i]]), "f"(v0), "f"(v1), "f"(ev), "f"(0.f)
                         : "memory");
        }
    }
}

// ---------------------------------------------------------------------------
// Kernel 3: normalize + bias -> output [N,2] float32
// ---------------------------------------------------------------------------
__global__ __launch_bounds__(256)
void gat_final_kernel(float* __restrict__ out,
                      const float* __restrict__ bias,
                      int N)
{
    int n = blockIdx.x * blockDim.x + threadIdx.x;
    if (n >= N) return;
    float4 a = g_acc[n];
    float inv = 1.0f / (a.z + 1e-16f);
    float b0 = __ldg(bias + 0), b1 = __ldg(bias + 1);
    ((float2*)out)[n] = make_float2(a.x * inv + b0, a.y * inv + b1);
}

// ---------------------------------------------------------------------------
// Input identification by element count (robust to metadata ordering):
//   x = largest; edge_index = 2nd; edge_attr = 3rd (gives E); W = 384;
//   att_src, att_dst, bias = the three size-2 tensors in appearance order.
// ---------------------------------------------------------------------------
extern "C" void kernel_launch(void* const* d_in, const int* in_sizes, int n_in,
                              void* d_out, int out_size)
{
    int i_x = -1, i_eidx = -1, i_attr = -1, i_W = -1;
    int small[3] = {-1, -1, -1};
    int nsmall = 0;
    {
        long long best = -1;
        for (int i = 0; i < n_in; i++)
            if (in_sizes[i] > best) { best = in_sizes[i]; i_x = i; }
        best = -1;
        for (int i = 0; i < n_in; i++)
            if (i != i_x && in_sizes[i] > best) { best = in_sizes[i]; i_eidx = i; }
        best = -1;
        for (int i = 0; i < n_in; i++)
            if (i != i_x && i != i_eidx && in_sizes[i] > best) { best = in_sizes[i]; i_attr = i; }
    }
    for (int i = 0; i < n_in; i++) {
        if (i == i_x || i == i_eidx || i == i_attr) continue;
        if (in_sizes[i] > 16) { i_W = i; }
        else if (nsmall < 3) { small[nsmall++] = i; }
    }

    const float* x       = (const float*)d_in[i_x];
    const void*  eidx    = d_in[i_eidx];
    const float* W       = (const float*)d_in[i_W];
    const float* att_src = (const float*)d_in[small[0]];
    const float* att_dst = (const float*)d_in[small[1]];
    const float* bias    = (const float*)d_in[small[2]];
    float* out           = (float*)d_out;

    int N = in_sizes[i_x] / IN_DIM;
    int E = in_sizes[i_attr];               // edge_attr is [E,1]
    int eidx_elems = in_sizes[i_eidx];

    // dtype resolution: ratio 4 => definitely int64 (word count); ratio 2 =>
    // sample odd words on device (single launch).
    if (eidx_elems == 4 * E) {
        detect_kernel<<<1, 1024>>>((const int*)eidx, 0, 1);
    } else {
        detect_kernel<<<1, 1024>>>((const int*)eidx, 2 * E, 1);
    }

    // K1: persistent warp loop; 1184 blocks x 8 warps = 9472 warps (full occ)
    gat_project_kernel<<<1184, 256>>>(x, W, att_src, att_dst, N);

    // K2: ILP=4 edges per thread
    int blocks2 = (E + 256 * EDGE_ILP - 1) / (256 * EDGE_ILP);
    gat_edge_kernel<<<blocks2, 256>>>(eidx, E, N);

    // K3: normalize + bias
    gat_final_kernel<<<(N + 255) / 256, 256>>>(out, bias, N);
}